// round 7
// baseline (speedup 1.0000x reference)
#include <cuda_runtime.h>
#include <cuda_fp16.h>
#include <cstdint>

#define NN      4096
#define FIN     256
#define FOUT    64
#define HEADS   4
#define NF      (NN * FOUT)
#define ITILE   64
#define JCHUNK  64
#define NSPLIT  2
#define NCHUNK  (NN / NSPLIT / JCHUNK)   // 32 chunks per block
#define ADJW    (NN / 32)                // 128 words per adj row

// ---------------- device scratch ----------------
__device__ float4   g_i4[NN * HEADS];            // {ei, exp(ei), exp(.2ei), 0}
__device__ float4   g_j4[NN * HEADS];            // {ej, exp(ej), exp(.2ej), 0}
__device__ __half   g_hT[HEADS * FOUT * NN];     // transposed h, fp16
__device__ unsigned g_adjb[NN * ADJW];           // bitmask: word (g,k) bit l <-> col 128g+4l+k
__device__ float    g_partC[NSPLIT * HEADS * NN * FOUT];  // unnormalized partial numerators
__device__ float    g_partZ[NSPLIT * HEADS * NN];         // partial denominators

// ---------------- PTX helpers (standard sm_75+ features only) ----------------
__device__ __forceinline__ uint32_t smem_u32(const void* p) {
    uint32_t a;
    asm("{ .reg .u64 t; cvta.to.shared.u64 t, %1; cvt.u32.u64 %0, t; }" : "=r"(a) : "l"(p));
    return a;
}
__device__ __forceinline__ void ldsm4(uint32_t* r, uint32_t addr) {
    asm volatile("ldmatrix.sync.aligned.m8n8.x4.shared.b16 {%0,%1,%2,%3}, [%4];"
                 : "=r"(r[0]), "=r"(r[1]), "=r"(r[2]), "=r"(r[3]) : "r"(addr));
}
__device__ __forceinline__ void mma16816(float* c, const uint32_t* a,
                                         uint32_t b0, uint32_t b1) {
    asm volatile("mma.sync.aligned.m16n8k16.row.col.f32.f16.f16.f32 "
                 "{%0,%1,%2,%3}, {%4,%5,%6,%7}, {%8,%9}, {%0,%1,%2,%3};"
                 : "+f"(c[0]), "+f"(c[1]), "+f"(c[2]), "+f"(c[3])
                 : "r"(a[0]), "r"(a[1]), "r"(a[2]), "r"(a[3]), "r"(b0), "r"(b1));
}
#define BAR_SYNC(id)   asm volatile("bar.sync %0, 256;"   :: "r"(id) : "memory")
#define BAR_ARRIVE(id) asm volatile("bar.arrive %0, 256;" :: "r"(id) : "memory")
// XOR swizzle: permute 16B chunks within a 128B row by row&7 (conflict-free LDSM)
__device__ __forceinline__ uint32_t swz(int row, int byteInRow) {
    return (uint32_t)(row * 128 + ((((byteInRow >> 4) ^ (row & 7)) << 4) | (byteInRow & 15)));
}

// ---------------- kernel 1: h = x @ W + fp16 hT + fused e-scores ----------------
__global__ void __launch_bounds__(256) gemm_h_kernel(const float* __restrict__ x,
                                                     const float* __restrict__ W,
                                                     const float* __restrict__ a) {
    __shared__ float xs[32][FIN];    // 32 KB; reused as h-tile for escore phase
    __shared__ float as[128];
    const int n0 = blockIdx.x * 32;
    const int t  = threadIdx.x;

    if (t < 128) as[t] = a[t];
    #pragma unroll
    for (int r = 0; r < 32; ++r) xs[r][t] = x[(n0 + r) * FIN + t];
    __syncthreads();

    float acc[32];
    #pragma unroll
    for (int r = 0; r < 32; ++r) acc[r] = 0.0f;

    for (int k = 0; k < FIN; k += 4) {
        const float w0 = W[(k + 0) * 256 + t];
        const float w1 = W[(k + 1) * 256 + t];
        const float w2 = W[(k + 2) * 256 + t];
        const float w3 = W[(k + 3) * 256 + t];
        #pragma unroll
        for (int r = 0; r < 32; ++r) {
            const float4 xv = *(const float4*)&xs[r][k];
            acc[r] = fmaf(xv.x, w0, acc[r]);
            acc[r] = fmaf(xv.y, w1, acc[r]);
            acc[r] = fmaf(xv.z, w2, acc[r]);
            acc[r] = fmaf(xv.w, w3, acc[r]);
        }
    }

    // thread t holds column t (= head*64+f) for rows n0..n0+31 -> direct hT write
    unsigned hp[16];
    #pragma unroll
    for (int r = 0; r < 32; r += 2) {
        const __half h0 = __float2half_rn(acc[r]);
        const __half h1 = __float2half_rn(acc[r + 1]);
        hp[r >> 1] = ((unsigned)__half_as_ushort(h1) << 16) | __half_as_ushort(h0);
    }
    uint4* dh = (uint4*)&g_hT[(size_t)t * NN + n0];
    #pragma unroll
    for (int q = 0; q < 4; ++q)
        dh[q] = make_uint4(hp[4 * q], hp[4 * q + 1], hp[4 * q + 2], hp[4 * q + 3]);

    // ---- fused escore: stage h-tile in smem, 64-wide dots, exp, store ----
    __syncthreads();
    #pragma unroll
    for (int r = 0; r < 32; ++r) xs[r][t] = acc[r];
    __syncthreads();

    {
        const int r     = t >> 3;        // 0..31
        const int g     = t & 7;
        const int hd    = g >> 1;
        const int which = g & 1;
        const float* av = as + which * 64;
        const float* hr = &xs[r][hd * 64];
        float s = 0.0f;
        #pragma unroll
        for (int f = 0; f < 64; ++f) s = fmaf(hr[f], av[f], s);
        const float4 v = make_float4(s, __expf(s), __expf(0.2f * s), 0.0f);
        if (which == 0) g_i4[(n0 + r) * HEADS + hd] = v;
        else            g_j4[(n0 + r) * HEADS + hd] = v;
    }
}

// ---------------- kernel 2: pack adj into bitmask (vectorized) ----------------
__global__ void __launch_bounds__(256) adj_pack_kernel(const int* __restrict__ adj) {
    const int row  = blockIdx.x * 8 + (threadIdx.x >> 5);
    const int lane = threadIdx.x & 31;
    const int4* ar = (const int4*)(adj + (size_t)row * NN);
    uint4* dst = (uint4*)(g_adjb + (size_t)row * ADJW);
    #pragma unroll 4
    for (int g = 0; g < 32; ++g) {
        const int4 v = ar[g * 32 + lane];
        const unsigned p0 = __ballot_sync(0xffffffffu, v.x != 0);
        const unsigned p1 = __ballot_sync(0xffffffffu, v.y != 0);
        const unsigned p2 = __ballot_sync(0xffffffffu, v.z != 0);
        const unsigned p3 = __ballot_sync(0xffffffffu, v.w != 0);
        if (lane == 0) dst[g] = make_uint4(p0, p1, p2, p3);
    }
}

// ---------------- kernel 3: warp-specialized mma attention ----------------
// Block = (64 i-rows, head, j-split). Warps 0-3 produce (gen Wt + stage Ht),
// warps 4-7 consume (mma). Double-buffered smem, named-barrier full/empty.
__global__ void __launch_bounds__(256, 2) gat_mma_kernel() {
    __shared__ __align__(128) __half Wt[2][ITILE * JCHUNK];   // 2 x 8 KB [i][j] swizzled
    __shared__ __align__(128) __half Ht[2][FOUT * JCHUNK];    // 2 x 8 KB [f][j] swizzled
    __shared__ float4 esm[ITILE];

    const int t     = threadIdx.x;
    const int lane  = t & 31;
    const int w     = t >> 5;
    const int head  = blockIdx.y;
    const int i0    = blockIdx.x * ITILE;
    const int split = blockIdx.z;
    const int jbase = split * (NN / NSPLIT);

    if (t < ITILE) esm[t] = g_i4[(i0 + t) * HEADS + head];

    const uint32_t wtb = smem_u32(Wt);
    const uint32_t htb = smem_u32(Ht);

    __syncthreads();   // esm ready

    if (w < 4) {
        // ================= PRODUCER =================
        const int p = w;
        const int kbase = (lane & 1) * 2;
        const int lbit  = lane >> 1;

        // Ht staging coords: 128 producer threads, 4 x uint4 each
        const int t128 = t;                 // 0..127
        const int hrow = t128 >> 1;         // 0..63
        const int hc16 = (t128 & 1) * 4;    // 16B-chunk base 0 or 4
        const __half* hsrc0 = &g_hT[(size_t)(head * FOUT + hrow) * NN + jbase];

        float z[16];
        #pragma unroll
        for (int r = 0; r < 16; ++r) z[r] = 0.0f;

        // prefetch regs
        float4 jd0, jd1;
        uint2  aw[16];
        uint4  hv[4];

        // prefetch chunk 0 (+ adj pair 0)
        jd0 = g_j4[(jbase + 2 * lane) * HEADS + head];
        jd1 = g_j4[(jbase + 2 * lane + 1) * HEADS + head];
        #pragma unroll
        for (int r = 0; r < 16; ++r)
            aw[r] = *(const uint2*)&g_adjb[(size_t)(i0 + p + 4 * r) * ADJW
                                           + split * (ADJW / NSPLIT) + kbase];
        #pragma unroll
        for (int q = 0; q < 4; ++q)
            hv[q] = *(const uint4*)(hsrc0 + (hc16 + q) * 8);

        for (int c = 0; c < NCHUNK; ++c) {
            const int b = c & 1;
            if (c >= 2) BAR_SYNC(3 + b);   // wait buffer b empty

            // ---- gen Wt rows {p, p+4, ...}: cols 2*lane, 2*lane+1 ----
            char* WtB = (char*)Wt[b];
            const int bit = ((c & 1) << 4) + lbit;
            #pragma unroll
            for (int r = 0; r < 16; ++r) {
                const int il = p + 4 * r;
                const float4 id = esm[il];
                const float s0 = id.x + jd0.x;
                const float s1 = id.x + jd1.x;
                float w0 = (s0 > 0.0f) ? id.y * jd0.y : id.z * jd0.z;
                float w1 = (s1 > 0.0f) ? id.y * jd1.y : id.z * jd1.z;
                w0 = ((aw[r].x >> bit) & 1u) ? w0 : 0.0f;
                w1 = ((aw[r].y >> bit) & 1u) ? w1 : 0.0f;
                z[r] += w0 + w1;
                *(__half2*)(WtB + swz(il, lane * 4)) = __floats2half2_rn(w0, w1);
            }
            // ---- stage Ht from prefetched regs ----
            char* HtB = (char*)Ht[b];
            #pragma unroll
            for (int q = 0; q < 4; ++q)
                *(uint4*)(HtB + swz(hrow, (hc16 + q) * 16)) = hv[q];

            // ---- prefetch chunk c+1 ----
            if (c + 1 < NCHUNK) {
                const int jn = jbase + (c + 1) * JCHUNK;
                jd0 = g_j4[(jn + 2 * lane) * HEADS + head];
                jd1 = g_j4[(jn + 2 * lane + 1) * HEADS + head];
                #pragma unroll
                for (int q = 0; q < 4; ++q)
                    hv[q] = *(const uint4*)(hsrc0 + (c + 1) * JCHUNK + (hc16 + q) * 8);
                if (c & 1) {   // reload adj word-pair for next even/odd chunk pair
                    const int gofs = split * (ADJW / NSPLIT) + ((c + 1) >> 1) * 4 + kbase;
                    #pragma unroll
                    for (int r = 0; r < 16; ++r)
                        aw[r] = *(const uint2*)&g_adjb[(size_t)(i0 + p + 4 * r) * ADJW + gofs];
                }
            }
            BAR_ARRIVE(1 + b);   // buffer b full
        }

        // ---- Z epilogue: reduce cols across lanes, store partial Z ----
        #pragma unroll
        for (int r = 0; r < 16; ++r) {
            float v = z[r];
            #pragma unroll
            for (int off = 16; off >= 1; off >>= 1)
                v += __shfl_xor_sync(0xffffffffu, v, off);
            if (lane == 0)
                g_partZ[(size_t)(split * HEADS + head) * NN + i0 + p + 4 * r] = v;
        }
    } else {
        // ================= CONSUMER =================
        const int q     = w - 4;
        const int mrow0 = q * 16;

        float acc[8][4];
        #pragma unroll
        for (int n = 0; n < 8; ++n)
            #pragma unroll
            for (int k = 0; k < 4; ++k) acc[n][k] = 0.0f;

        for (int c = 0; c < NCHUNK; ++c) {
            const int b = c & 1;
            BAR_SYNC(1 + b);   // wait buffer b full

            const uint32_t wb = wtb + b * (ITILE * JCHUNK * 2);
            const uint32_t hb = htb + b * (FOUT * JCHUNK * 2);
            #pragma unroll
            for (int ks = 0; ks < 4; ++ks) {
                uint32_t af[4];
                {
                    const int arow = mrow0 + (lane & 15);
                    const int akc  = ks * 2 + (lane >> 4);
                    ldsm4(af, wb + swz(arow, akc * 16));
                }
                #pragma unroll
                for (int np = 0; np < 4; ++np) {
                    uint32_t bf[4];
                    const int grp  = lane >> 3;
                    const int brow = np * 16 + (grp >> 1) * 8 + (lane & 7);
                    const int bkc  = ks * 2 + (grp & 1);
                    ldsm4(bf, hb + swz(brow, bkc * 16));
                    mma16816(acc[np * 2],     af, bf[0], bf[1]);
                    mma16816(acc[np * 2 + 1], af, bf[2], bf[3]);
                }
            }
            BAR_ARRIVE(3 + b);   // buffer b empty
        }

        // ---- epilogue: store unnormalized partial C ----
        const int qq = lane >> 2;
        const int i2 = (lane & 3) * 2;
        const int r0 = mrow0 + qq;
        const int r1 = mrow0 + qq + 8;
        float* base = g_partC + (size_t)(split * HEADS + head) * NN * FOUT;
        float* p0 = base + (size_t)(i0 + r0) * FOUT + i2;
        float* p1 = base + (size_t)(i0 + r1) * FOUT + i2;
        #pragma unroll
        for (int nt = 0; nt < 8; ++nt) {
            *(float2*)(p0 + nt * 8) = make_float2(acc[nt][0], acc[nt][1]);
            *(float2*)(p1 + nt * 8) = make_float2(acc[nt][2], acc[nt][3]);
        }
    }
}

// ---------------- kernel 4: combine splits, normalize, mean heads ----------
__global__ void __launch_bounds__(256) combine_kernel(float* __restrict__ out) {
    const int idx = blockIdx.x * 256 + threadIdx.x;   // i*64 + f
    const int i = idx >> 6;
    float r = 0.0f;
    #pragma unroll
    for (int h = 0; h < HEADS; ++h) {
        const float c = g_partC[(size_t)h * NN * FOUT + idx] +
                        g_partC[(size_t)(HEADS + h) * NN * FOUT + idx];
        const float z = g_partZ[(size_t)h * NN + i] +
                        g_partZ[(size_t)(HEADS + h) * NN + i];
        r += c / z;
    }
    out[idx] = 0.25f * r;
}

// ---------------- launcher ----------------
extern "C" void kernel_launch(void* const* d_in, const int* in_sizes, int n_in,
                              void* d_out, int out_size) {
    const float* x = nullptr;
    const int*   adj = nullptr;
    const float* W = nullptr;
    const float* a = nullptr;
    for (int i = 0; i < n_in; ++i) {
        switch (in_sizes[i]) {
            case 1048576:  x   = (const float*)d_in[i]; break;
            case 16777216: adj = (const int*)  d_in[i]; break;
            case 65536:    W   = (const float*)d_in[i]; break;
            case 128:      a   = (const float*)d_in[i]; break;
        }
    }
    float* out = (float*)d_out;

    gemm_h_kernel<<<NN / 32, 256>>>(x, W, a);
    adj_pack_kernel<<<NN / 8, 256>>>(adj);
    gat_mma_kernel<<<dim3(NN / ITILE, HEADS, NSPLIT), 256>>>();
    combine_kernel<<<NF / 256, 256>>>(out);
}

// round 8
// speedup vs baseline: 1.5141x; 1.5141x over previous
#include <cuda_runtime.h>
#include <cuda_fp16.h>
#include <cstdint>

#define NN      4096
#define FIN     256
#define FOUT    64
#define HEADS   4
#define NF      (NN * FOUT)
#define ITILE   128
#define JCHUNK  64
#define NSPLIT  4
#define NCHUNK  (NN / NSPLIT / JCHUNK)   // 16 chunks per block
#define NCH_ROW (NN / JCHUNK)            // 64 chunk-masks per adj row
#define HT_B    (FOUT * JCHUNK * 2)      // 8192 bytes per Ht buffer

// ---------------- device scratch ----------------
__device__ float4 g_i4[NN * HEADS];            // {ei, exp(ei), exp(.2ei), 0}
__device__ float4 g_j4[NN * HEADS];            // {ej, exp(ej), exp(.2ej), 0}
__device__ __half g_hT[HEADS * FOUT * NN];     // transposed h, fp16
__device__ uint2  g_adjb2[NN * NCH_ROW];       // 64-bit mask per (row, 64-col chunk):
                                               //   word.x bit b = col 64c+b, word.y bit b = col 64c+32+b
__device__ float  g_partC[NSPLIT * HEADS * NN * FOUT];  // unnormalized partial numerators
__device__ float  g_partZ[NSPLIT * HEADS * NN];         // partial denominators

// ---------------- PTX helpers ----------------
__device__ __forceinline__ uint32_t smem_u32(const void* p) {
    uint32_t a;
    asm("{ .reg .u64 t; cvta.to.shared.u64 t, %1; cvt.u32.u64 %0, t; }" : "=r"(a) : "l"(p));
    return a;
}
__device__ __forceinline__ void ldsm4(uint32_t* r, uint32_t addr) {
    asm volatile("ldmatrix.sync.aligned.m8n8.x4.shared.b16 {%0,%1,%2,%3}, [%4];"
                 : "=r"(r[0]), "=r"(r[1]), "=r"(r[2]), "=r"(r[3]) : "r"(addr));
}
__device__ __forceinline__ void mma16816(float* c, const uint32_t* a,
                                         uint32_t b0, uint32_t b1) {
    asm volatile("mma.sync.aligned.m16n8k16.row.col.f32.f16.f16.f32 "
                 "{%0,%1,%2,%3}, {%4,%5,%6,%7}, {%8,%9}, {%0,%1,%2,%3};"
                 : "+f"(c[0]), "+f"(c[1]), "+f"(c[2]), "+f"(c[3])
                 : "r"(a[0]), "r"(a[1]), "r"(a[2]), "r"(a[3]), "r"(b0), "r"(b1));
}
#define CP_ASYNC16(dst, src) \
    asm volatile("cp.async.cg.shared.global [%0], [%1], 16;" :: "r"(dst), "l"(src) : "memory")
#define CP_COMMIT() asm volatile("cp.async.commit_group;" ::: "memory")
#define CP_WAIT1()  asm volatile("cp.async.wait_group 1;"  ::: "memory")
// XOR swizzle: permute 16B chunks within a 128B row by row&7 (conflict-free LDSM)
__device__ __forceinline__ uint32_t swz(int row, int byteInRow) {
    return (uint32_t)(row * 128 + ((((byteInRow >> 4) ^ (row & 7)) << 4) | (byteInRow & 15)));
}
// GATv2 factored weight: s = ei+ej; w = s>0 ? e^ei e^ej : e^.2ei e^.2ej; masked
__device__ __forceinline__ float gatw(const float4 e, const float4 j, unsigned bit) {
    const float s = e.x + j.x;
    const float p = (s > 0.0f) ? e.y * j.y : e.z * j.z;
    return bit ? p : 0.0f;
}
__device__ __forceinline__ uint32_t packh2(float a, float b) {
    const __half2 h = __floats2half2_rn(a, b);   // .x = a (low) -> col c, .y = b -> col c+1
    return *reinterpret_cast<const uint32_t*>(&h);
}

// ---------------- kernel 1: h = x @ W + fp16 hT + fused e-scores ----------------
__global__ void __launch_bounds__(256) gemm_h_kernel(const float* __restrict__ x,
                                                     const float* __restrict__ W,
                                                     const float* __restrict__ a) {
    __shared__ float xs[32][FIN];    // 32 KB; reused as h-tile for escore phase
    __shared__ float as[128];
    const int n0 = blockIdx.x * 32;
    const int t  = threadIdx.x;

    if (t < 128) as[t] = a[t];
    #pragma unroll
    for (int r = 0; r < 32; ++r) xs[r][t] = x[(n0 + r) * FIN + t];
    __syncthreads();

    float acc[32];
    #pragma unroll
    for (int r = 0; r < 32; ++r) acc[r] = 0.0f;

    for (int k = 0; k < FIN; k += 4) {
        const float w0 = W[(k + 0) * 256 + t];
        const float w1 = W[(k + 1) * 256 + t];
        const float w2 = W[(k + 2) * 256 + t];
        const float w3 = W[(k + 3) * 256 + t];
        #pragma unroll
        for (int r = 0; r < 32; ++r) {
            const float4 xv = *(const float4*)&xs[r][k];
            acc[r] = fmaf(xv.x, w0, acc[r]);
            acc[r] = fmaf(xv.y, w1, acc[r]);
            acc[r] = fmaf(xv.z, w2, acc[r]);
            acc[r] = fmaf(xv.w, w3, acc[r]);
        }
    }

    // thread t holds column t (= head*64+f) for rows n0..n0+31 -> direct hT write
    unsigned hp[16];
    #pragma unroll
    for (int r = 0; r < 32; r += 2) {
        const __half h0 = __float2half_rn(acc[r]);
        const __half h1 = __float2half_rn(acc[r + 1]);
        hp[r >> 1] = ((unsigned)__half_as_ushort(h1) << 16) | __half_as_ushort(h0);
    }
    uint4* dh = (uint4*)&g_hT[(size_t)t * NN + n0];
    #pragma unroll
    for (int q = 0; q < 4; ++q)
        dh[q] = make_uint4(hp[4 * q], hp[4 * q + 1], hp[4 * q + 2], hp[4 * q + 3]);

    // ---- fused escore: stage h-tile in smem, 64-wide dots, exp, store ----
    __syncthreads();
    #pragma unroll
    for (int r = 0; r < 32; ++r) xs[r][t] = acc[r];
    __syncthreads();

    {
        const int r     = t >> 3;        // 0..31
        const int g     = t & 7;
        const int hd    = g >> 1;
        const int which = g & 1;
        const float* av = as + which * 64;
        const float* hr = &xs[r][hd * 64];
        float s = 0.0f;
        #pragma unroll
        for (int f = 0; f < 64; ++f) s = fmaf(hr[f], av[f], s);
        const float4 v = make_float4(s, __expf(s), __expf(0.2f * s), 0.0f);
        if (which == 0) g_i4[(n0 + r) * HEADS + hd] = v;
        else            g_j4[(n0 + r) * HEADS + hd] = v;
    }
}

// ---------------- kernel 2: pack adj -> 64-bit chunk masks ----------------
__global__ void __launch_bounds__(256) adj_pack_kernel(const int* __restrict__ adj) {
    const int row  = blockIdx.x * 8 + (threadIdx.x >> 5);
    const int lane = threadIdx.x & 31;
    const int* ar = adj + (size_t)row * NN;
    #pragma unroll 4
    for (int c = 0; c < NCH_ROW; ++c) {
        const int v0 = ar[c * 64 + lane];
        const int v1 = ar[c * 64 + 32 + lane];
        const unsigned b0 = __ballot_sync(0xffffffffu, v0 != 0);
        const unsigned b1 = __ballot_sync(0xffffffffu, v1 != 0);
        if (lane == 0) g_adjb2[(size_t)row * NCH_ROW + c] = make_uint2(b0, b1);
    }
}

// ---------------- kernel 3: register-gen A-fragment mma attention ----------------
// Block = (128 i-rows, head, j-split of 1024). Warp w owns rows w*16..+16, all 64 f.
// Per chunk: cp.async-staged Ht[64f x 64j] + jd tile; A fragments GENERATED in
// registers (no Wt smem / STS / LDSM-A); Z in registers.
__global__ void __launch_bounds__(256, 2) gat_mma_kernel() {
    __shared__ __align__(128) __half  Ht[3][FOUT * JCHUNK];   // 3 x 8 KB [f][j] swizzled
    __shared__ __align__(16)  float4  jds[3][JCHUNK];         // 3 x 1 KB

    const int t     = threadIdx.x;
    const int lane  = t & 31;
    const int w     = t >> 5;
    const int tid   = lane & 3;
    const int gr    = lane >> 2;
    const int head  = blockIdx.y;
    const int i0    = blockIdx.x * ITILE;
    const int split = blockIdx.z;
    const int jbase = split * (NN / NSPLIT);
    const int cg0   = split * NCHUNK;

    const uint32_t htb = smem_u32(Ht);

    // per-thread row pair (A-fragment layout): rows rA, rA+8
    const int rA = w * 16 + gr;
    const float4 e0 = g_i4[(i0 + rA) * HEADS + head];
    const float4 e1 = g_i4[(i0 + rA + 8) * HEADS + head];

    // Ht staging coords: thread covers (row t>>2, 16B segs s0,s0+1)
    const int hrow = t >> 2;
    const int s0   = (t & 3) * 2;
    const __half* hsrc = &g_hT[(size_t)(head * FOUT + hrow) * NN + jbase];

    // adj masks, double-buffered in regs
    const uint2* adjr0 = &g_adjb2[(size_t)(i0 + rA) * NCH_ROW + cg0];
    const uint2* adjr1 = &g_adjb2[(size_t)(i0 + rA + 8) * NCH_ROW + cg0];
    uint2 awc0 = adjr0[0], awc1 = adjr1[0];
    uint2 awn0, awn1;

    float acc[8][4];
    #pragma unroll
    for (int n = 0; n < 8; ++n)
        #pragma unroll
        for (int k = 0; k < 4; ++k) acc[n][k] = 0.0f;
    float z0 = 0.0f, z1 = 0.0f;

    // ---- prologue: stage chunks 0,1 ----
    #pragma unroll
    for (int pc = 0; pc < 2; ++pc) {
        const uint32_t hb = htb + pc * HT_B;
        CP_ASYNC16(hb + swz(hrow, s0 * 16),       hsrc + pc * JCHUNK + s0 * 8);
        CP_ASYNC16(hb + swz(hrow, (s0 + 1) * 16), hsrc + pc * JCHUNK + (s0 + 1) * 8);
        if (t < JCHUNK)
            CP_ASYNC16(smem_u32(&jds[pc][t]), &g_j4[(jbase + pc * JCHUNK + t) * HEADS + head]);
        CP_COMMIT();
    }

    for (int c = 0; c < NCHUNK; ++c) {
        const int b = c % 3;
        CP_WAIT1();
        __syncthreads();

        // ---- issue chunk c+2 into buffer (c+2)%3 (its last readers were chunk c-1) ----
        if (c + 2 < NCHUNK) {
            const int b2 = (c + 2) % 3;
            const uint32_t hb = htb + b2 * HT_B;
            CP_ASYNC16(hb + swz(hrow, s0 * 16),       hsrc + (c + 2) * JCHUNK + s0 * 8);
            CP_ASYNC16(hb + swz(hrow, (s0 + 1) * 16), hsrc + (c + 2) * JCHUNK + (s0 + 1) * 8);
            if (t < JCHUNK)
                CP_ASYNC16(smem_u32(&jds[b2][t]),
                           &g_j4[(jbase + (c + 2) * JCHUNK + t) * HEADS + head]);
        }
        CP_COMMIT();   // always commit (keeps wait_group accounting correct)

        // ---- prefetch next chunk's adj masks ----
        if (c + 1 < NCHUNK) { awn0 = adjr0[c + 1]; awn1 = adjr1[c + 1]; }

        const uint32_t hb = htb + b * HT_B;
        const float4* jrow = jds[b];

        #pragma unroll
        for (int ks = 0; ks < 4; ++ks) {
            // B fragments: 4 n-tiles of 16 f-cols
            uint32_t bf[4][4];
            {
                const int grp  = lane >> 3;
                const int bkcB = (ks * 2 + (grp & 1)) * 16;
                const int rofs = (grp >> 1) * 8 + (lane & 7);
                #pragma unroll
                for (int np = 0; np < 4; ++np)
                    ldsm4(bf[np], hb + swz(np * 16 + rofs, bkcB));
            }
            // jd factors for this thread's 4 columns
            const float4 ja = jrow[ks * 16 + 2 * tid];
            const float4 jb = jrow[ks * 16 + 2 * tid + 1];
            const float4 jc = jrow[ks * 16 + 2 * tid + 8];
            const float4 jd = jrow[ks * 16 + 2 * tid + 9];
            // adj bits: ks 0,1 -> word.x ; ks 2,3 -> word.y
            const unsigned m0 = (ks < 2) ? awc0.x : awc0.y;
            const unsigned m1 = (ks < 2) ? awc1.x : awc1.y;
            const int base = (ks & 1) * 16 + 2 * tid;
            const unsigned b0 = m0 >> base;
            const unsigned b1 = m1 >> base;
            // generate A fragment in registers (m16n8k16 layout)
            const float w00 = gatw(e0, ja, b0 & 1u);
            const float w01 = gatw(e0, jb, (b0 >> 1) & 1u);
            const float w10 = gatw(e1, ja, b1 & 1u);
            const float w11 = gatw(e1, jb, (b1 >> 1) & 1u);
            const float w02 = gatw(e0, jc, (b0 >> 8) & 1u);
            const float w03 = gatw(e0, jd, (b0 >> 9) & 1u);
            const float w12 = gatw(e1, jc, (b1 >> 8) & 1u);
            const float w13 = gatw(e1, jd, (b1 >> 9) & 1u);
            z0 += (w00 + w01) + (w02 + w03);
            z1 += (w10 + w11) + (w12 + w13);
            uint32_t af[4];
            af[0] = packh2(w00, w01);
            af[1] = packh2(w10, w11);
            af[2] = packh2(w02, w03);
            af[3] = packh2(w12, w13);
            // 8 HMMA (bf loaded ~50 instrs ago -> no stall)
            #pragma unroll
            for (int np = 0; np < 4; ++np) {
                mma16816(acc[np * 2],     af, bf[np][0], bf[np][1]);
                mma16816(acc[np * 2 + 1], af, bf[np][2], bf[np][3]);
            }
        }
        awc0 = awn0;
        awc1 = awn1;
    }

    // ---- Z: quad reduce (lanes of a quad cover disjoint cols of same rows) ----
    z0 += __shfl_xor_sync(0xffffffffu, z0, 1);
    z0 += __shfl_xor_sync(0xffffffffu, z0, 2);
    z1 += __shfl_xor_sync(0xffffffffu, z1, 1);
    z1 += __shfl_xor_sync(0xffffffffu, z1, 2);
    if (tid == 0) {
        float* zb = g_partZ + (size_t)(split * HEADS + head) * NN + i0;
        zb[rA]     = z0;
        zb[rA + 8] = z1;
    }

    // ---- epilogue: store unnormalized partial C ----
    {
        float* cbase = g_partC + (size_t)(split * HEADS + head) * NN * FOUT;
        float* p0 = cbase + (size_t)(i0 + rA) * FOUT + 2 * tid;
        float* p1 = cbase + (size_t)(i0 + rA + 8) * FOUT + 2 * tid;
        #pragma unroll
        for (int np = 0; np < 4; ++np) {
            #pragma unroll
            for (int p = 0; p < 2; ++p) {
                const int nt = np * 2 + p;
                const int cb = np * 16 + p * 8;
                *(float2*)(p0 + cb) = make_float2(acc[nt][0], acc[nt][1]);
                *(float2*)(p1 + cb) = make_float2(acc[nt][2], acc[nt][3]);
            }
        }
    }
}

// ---------------- kernel 4: combine splits, normalize, mean heads ----------
__global__ void __launch_bounds__(256) combine_kernel(float* __restrict__ out) {
    const int idx = blockIdx.x * 256 + threadIdx.x;   // i*64 + f
    const int i = idx >> 6;
    float r = 0.0f;
    #pragma unroll
    for (int h = 0; h < HEADS; ++h) {
        float cs = 0.0f, zs = 0.0f;
        #pragma unroll
        for (int s = 0; s < NSPLIT; ++s) {
            cs += g_partC[(size_t)(s * HEADS + h) * NN * FOUT + idx];
            zs += g_partZ[(size_t)(s * HEADS + h) * NN + i];
        }
        r += cs / zs;
    }
    out[idx] = 0.25f * r;
}

// ---------------- launcher ----------------
extern "C" void kernel_launch(void* const* d_in, const int* in_sizes, int n_in,
                              void* d_out, int out_size) {
    const float* x = nullptr;
    const int*   adj = nullptr;
    const float* W = nullptr;
    const float* a = nullptr;
    for (int i = 0; i < n_in; ++i) {
        switch (in_sizes[i]) {
            case 1048576:  x   = (const float*)d_in[i]; break;
            case 16777216: adj = (const int*)  d_in[i]; break;
            case 65536:    W   = (const float*)d_in[i]; break;
            case 128:      a   = (const float*)d_in[i]; break;
        }
    }
    float* out = (float*)d_out;

    gemm_h_kernel<<<NN / 32, 256>>>(x, W, a);
    adj_pack_kernel<<<NN / 8, 256>>>(adj);
    gat_mma_kernel<<<dim3(NN / ITILE, HEADS, NSPLIT), 256>>>();
    combine_kernel<<<NF / 256, 256>>>(out);
}

// round 9
// speedup vs baseline: 1.8151x; 1.1988x over previous
#include <cuda_runtime.h>
#include <cuda_fp16.h>
#include <cstdint>

#define NN      4096
#define FIN     256
#define FOUT    64
#define HEADS   4
#define NF      (NN * FOUT)
#define ITILE   128
#define JCHUNK  64
#define NSPLIT  2
#define NCHUNK  (NN / NSPLIT / JCHUNK)   // 32 chunks per block
#define NCH_ROW (NN / JCHUNK)            // 64 chunk-masks per adj row
#define HT_B    (FOUT * JCHUNK * 2)      // 8192 bytes per Ht buffer
#define GROWS   16                       // rows per gemm_h block

// ---------------- device scratch ----------------
__device__ float4 g_i4[NN * HEADS];            // {ei, exp(ei), exp(.2ei), 0}
__device__ uint2  g_jh2[HEADS * (NN / 2)];     // per (head, node-pair): {E2, N2} half2s
__device__ __half g_hT[HEADS * FOUT * NN];     // transposed h, fp16
__device__ uint2  g_adjb2[NN * NCH_ROW];       // 64-bit mask per (row, 64-col chunk)
__device__ float  g_partC[NSPLIT * HEADS * NN * FOUT];
__device__ float  g_partZ[NSPLIT * HEADS * NN];

// ---------------- PTX helpers ----------------
__device__ __forceinline__ uint32_t smem_u32(const void* p) {
    uint32_t a;
    asm("{ .reg .u64 t; cvta.to.shared.u64 t, %1; cvt.u32.u64 %0, t; }" : "=r"(a) : "l"(p));
    return a;
}
__device__ __forceinline__ void ldsm4(uint32_t* r, uint32_t addr) {
    asm volatile("ldmatrix.sync.aligned.m8n8.x4.shared.b16 {%0,%1,%2,%3}, [%4];"
                 : "=r"(r[0]), "=r"(r[1]), "=r"(r[2]), "=r"(r[3]) : "r"(addr));
}
__device__ __forceinline__ void ldsm2(uint32_t& r0, uint32_t& r1, uint32_t addr) {
    asm volatile("ldmatrix.sync.aligned.m8n8.x2.shared.b16 {%0,%1}, [%2];"
                 : "=r"(r0), "=r"(r1) : "r"(addr));
}
__device__ __forceinline__ void mma16816(float* c, const uint32_t* a,
                                         uint32_t b0, uint32_t b1) {
    asm volatile("mma.sync.aligned.m16n8k16.row.col.f32.f16.f16.f32 "
                 "{%0,%1,%2,%3}, {%4,%5,%6,%7}, {%8,%9}, {%0,%1,%2,%3};"
                 : "+f"(c[0]), "+f"(c[1]), "+f"(c[2]), "+f"(c[3])
                 : "r"(a[0]), "r"(a[1]), "r"(a[2]), "r"(a[3]), "r"(b0), "r"(b1));
}
#define CP_ASYNC16(dst, src) \
    asm volatile("cp.async.cg.shared.global [%0], [%1], 16;" :: "r"(dst), "l"(src) : "memory")
#define CP_ASYNC8(dst, src) \
    asm volatile("cp.async.ca.shared.global [%0], [%1], 8;"  :: "r"(dst), "l"(src) : "memory")
#define CP_COMMIT() asm volatile("cp.async.commit_group;" ::: "memory")
#define CP_WAIT1()  asm volatile("cp.async.wait_group 1;"  ::: "memory")
// XOR swizzle: permute 16B chunks within a 128B row by row&7 (conflict-free LDSM)
__device__ __forceinline__ uint32_t swz(int row, int byteInRow) {
    return (uint32_t)(row * 128 + ((((byteInRow >> 4) ^ (row & 7)) << 4) | (byteInRow & 15)));
}
// w2 = max(Ei*Ej, Ni*Nj) in half2, then AND with 2-bit-derived lane mask
__device__ __forceinline__ uint32_t wgen(__half2 hE, __half2 hN,
                                         uint32_t Ep, uint32_t Np, unsigned b2) {
    const __half2 Eh = *reinterpret_cast<const __half2*>(&Ep);
    const __half2 Nh = *reinterpret_cast<const __half2*>(&Np);
    const __half2 w2 = __hmax2(__hmul2(hE, Eh), __hmul2(hN, Nh));
    const uint32_t m = ((b2 & 1u) * 0xFFFFu) | (((b2 >> 1) & 1u) * 0xFFFF0000u);
    return (*reinterpret_cast<const uint32_t*>(&w2)) & m;
}

// ---------------- kernel 1: x@W + hT + e-scores + adj pack (all fused) ----------------
__global__ void __launch_bounds__(256) gemm_h_kernel(const float* __restrict__ x,
                                                     const float* __restrict__ W,
                                                     const float* __restrict__ a,
                                                     const int* __restrict__ adj) {
    __shared__ float xs[GROWS][FIN];   // 16 KB
    __shared__ float as[128];
    const int n0 = blockIdx.x * GROWS;
    const int t  = threadIdx.x;
    const int lane = t & 31;
    const int ww   = t >> 5;

    if (t < 128) as[t] = a[t];
    #pragma unroll
    for (int r = 0; r < GROWS; ++r) xs[r][t] = x[(n0 + r) * FIN + t];
    __syncthreads();

    float acc[GROWS];
    #pragma unroll
    for (int r = 0; r < GROWS; ++r) acc[r] = 0.0f;

    for (int k = 0; k < FIN; k += 4) {
        const float w0 = W[(k + 0) * 256 + t];
        const float w1 = W[(k + 1) * 256 + t];
        const float w2 = W[(k + 2) * 256 + t];
        const float w3 = W[(k + 3) * 256 + t];
        #pragma unroll
        for (int r = 0; r < GROWS; ++r) {
            const float4 xv = *(const float4*)&xs[r][k];
            acc[r] = fmaf(xv.x, w0, acc[r]);
            acc[r] = fmaf(xv.y, w1, acc[r]);
            acc[r] = fmaf(xv.z, w2, acc[r]);
            acc[r] = fmaf(xv.w, w3, acc[r]);
        }
    }

    // thread t holds column t (= head*64+f) for rows n0..n0+15 -> direct hT write
    unsigned hp[GROWS / 2];
    #pragma unroll
    for (int r = 0; r < GROWS; r += 2) {
        const __half h0 = __float2half_rn(acc[r]);
        const __half h1 = __float2half_rn(acc[r + 1]);
        hp[r >> 1] = ((unsigned)__half_as_ushort(h1) << 16) | __half_as_ushort(h0);
    }
    uint4* dh = (uint4*)&g_hT[(size_t)t * NN + n0];
    #pragma unroll
    for (int q = 0; q < GROWS / 8; ++q)
        dh[q] = make_uint4(hp[4 * q], hp[4 * q + 1], hp[4 * q + 2], hp[4 * q + 3]);

    // ---- fused escore: stage h-tile in smem, 64-wide dots ----
    __syncthreads();
    #pragma unroll
    for (int r = 0; r < GROWS; ++r) xs[r][t] = acc[r];
    __syncthreads();

    if (t < 128) {
        const int r     = t >> 3;        // 0..15
        const int g     = t & 7;
        const int hd    = g >> 1;
        const int which = g & 1;
        const float* av = as + which * 64;
        const float* hr = &xs[r][hd * 64];
        float s = 0.0f;
        #pragma unroll
        for (int f = 0; f < 64; ++f) s = fmaf(hr[f], av[f], s);
        const int n = n0 + r;
        const float E = __expf(s);
        const float N = __expf(0.2f * s);
        if (which == 0) {
            g_i4[n * HEADS + hd] = make_float4(s, E, N, 0.0f);
        } else {
            __half* jb = (__half*)&g_jh2[(size_t)hd * (NN / 2) + (n >> 1)];
            jb[n & 1]       = __float2half_rn(E);
            jb[2 + (n & 1)] = __float2half_rn(N);
        }
    }

    // ---- fused adj pack: warp ww packs rows n0+2ww, n0+2ww+1 ----
    {
        const int row0 = n0 + 2 * ww;
        const int* ar0 = adj + (size_t)row0 * NN;
        const int* ar1 = ar0 + NN;
        uint2* d0 = &g_adjb2[(size_t)row0 * NCH_ROW];
        uint2* d1 = d0 + NCH_ROW;
        #pragma unroll 2
        for (int c = 0; c < NCH_ROW; ++c) {
            const int va = ar0[c * 64 + lane];
            const int vb = ar0[c * 64 + 32 + lane];
            const int vc = ar1[c * 64 + lane];
            const int vd = ar1[c * 64 + 32 + lane];
            const unsigned ba = __ballot_sync(0xffffffffu, va != 0);
            const unsigned bb = __ballot_sync(0xffffffffu, vb != 0);
            const unsigned bc = __ballot_sync(0xffffffffu, vc != 0);
            const unsigned bd = __ballot_sync(0xffffffffu, vd != 0);
            if (lane == 0) { d0[c] = make_uint2(ba, bb); d1[c] = make_uint2(bc, bd); }
        }
    }
}

// ---------------- kernel 2: register-gen mma attention (half2 max-trick, Z via MMA) --
__global__ void __launch_bounds__(256, 2) gat_mma_kernel() {
    __shared__ __align__(128) __half  Ht[3][FOUT * JCHUNK];   // 3 x 8 KB [f][j] swizzled
    __shared__ __align__(16)  uint2   jsm[3][JCHUNK / 2];     // 3 x 256 B {E2,N2} per pair
    __shared__ __align__(32)  __half  OnesT[8][16];           // B-tile: row0(n=0) = ones

    const int t     = threadIdx.x;
    const int lane  = t & 31;
    const int w     = t >> 5;
    const int tid   = lane & 3;
    const int gr    = lane >> 2;
    const int head  = blockIdx.y;
    const int i0    = blockIdx.x * ITILE;
    const int split = blockIdx.z;
    const int jbase = split * (NN / NSPLIT);
    const int cg0   = split * NCHUNK;

    const uint32_t htb = smem_u32(Ht);
    const uint32_t onb = smem_u32(OnesT);

    if (t < 128) ((__half*)OnesT)[t] = (t < 16) ? __float2half(1.0f) : __float2half(0.0f);

    // per-thread row pair (A-fragment layout): rows rA, rA+8
    const int rA = w * 16 + gr;
    const float4 e0 = g_i4[(i0 + rA) * HEADS + head];
    const float4 e1 = g_i4[(i0 + rA + 8) * HEADS + head];
    const __half2 hE0 = __float2half2_rn(e0.y), hN0 = __float2half2_rn(e0.z);
    const __half2 hE1 = __float2half2_rn(e1.y), hN1 = __float2half2_rn(e1.z);

    // Ht staging coords
    const int hrow = t >> 2;
    const int s0   = (t & 3) * 2;
    const __half* hsrc = &g_hT[(size_t)(head * FOUT + hrow) * NN + jbase];
    const uint2* jsrc = &g_jh2[(size_t)head * (NN / 2) + jbase / 2];

    // adj masks, double-buffered in regs
    const uint2* adjr0 = &g_adjb2[(size_t)(i0 + rA) * NCH_ROW + cg0];
    const uint2* adjr1 = &g_adjb2[(size_t)(i0 + rA + 8) * NCH_ROW + cg0];
    uint2 awc0 = adjr0[0], awc1 = adjr1[0];
    uint2 awn0, awn1;

    float acc[8][4];
    #pragma unroll
    for (int n = 0; n < 8; ++n)
        #pragma unroll
        for (int k = 0; k < 4; ++k) acc[n][k] = 0.0f;
    float accZ[4] = {0.0f, 0.0f, 0.0f, 0.0f};

    // ---- prologue: stage chunks 0,1 ----
    #pragma unroll
    for (int pc = 0; pc < 2; ++pc) {
        const uint32_t hb = htb + pc * HT_B;
        CP_ASYNC16(hb + swz(hrow, s0 * 16),       hsrc + pc * JCHUNK + s0 * 8);
        CP_ASYNC16(hb + swz(hrow, (s0 + 1) * 16), hsrc + pc * JCHUNK + (s0 + 1) * 8);
        if (t < JCHUNK / 2)
            CP_ASYNC8(smem_u32(&jsm[pc][t]), jsrc + pc * (JCHUNK / 2) + t);
        CP_COMMIT();
    }

    __syncthreads();   // OnesT visible
    uint32_t oz0, oz1;
    ldsm2(oz0, oz1, onb + (lane & 7) * 32 + ((lane >> 3) & 1) * 16);

    for (int c = 0; c < NCHUNK; ++c) {
        const int b = c % 3;
        CP_WAIT1();
        __syncthreads();

        // ---- issue chunk c+2 into buffer (c+2)%3 ----
        if (c + 2 < NCHUNK) {
            const int b2 = (c + 2) % 3;
            const uint32_t hb = htb + b2 * HT_B;
            CP_ASYNC16(hb + swz(hrow, s0 * 16),       hsrc + (c + 2) * JCHUNK + s0 * 8);
            CP_ASYNC16(hb + swz(hrow, (s0 + 1) * 16), hsrc + (c + 2) * JCHUNK + (s0 + 1) * 8);
            if (t < JCHUNK / 2)
                CP_ASYNC8(smem_u32(&jsm[b2][t]), jsrc + (c + 2) * (JCHUNK / 2) + t);
        }
        CP_COMMIT();

        if (c + 1 < NCHUNK) { awn0 = adjr0[c + 1]; awn1 = adjr1[c + 1]; }

        const uint32_t hb = htb + b * HT_B;
        const uint2* jrow = jsm[b];

        #pragma unroll
        for (int ks = 0; ks < 4; ++ks) {
            // B fragments: 4 n-tiles of 16 f-cols
            uint32_t bf[4][4];
            {
                const int grp  = lane >> 3;
                const int bkcB = (ks * 2 + (grp & 1)) * 16;
                const int rofs = (grp >> 1) * 8 + (lane & 7);
                #pragma unroll
                for (int np = 0; np < 4; ++np)
                    ldsm4(bf[np], hb + swz(np * 16 + rofs, bkcB));
            }
            // j factors: pair A = cols {ks*16+2tid, +1}, pair B = +8
            const uint2 jA = jrow[ks * 8 + tid];
            const uint2 jB = jrow[ks * 8 + tid + 4];
            // adj bits
            const unsigned m0 = (ks < 2) ? awc0.x : awc0.y;
            const unsigned m1 = (ks < 2) ? awc1.x : awc1.y;
            const int base = (ks & 1) * 16 + 2 * tid;
            const unsigned r0b = m0 >> base;
            const unsigned r1b = m1 >> base;
            // generate A fragment: w = max(Ei*Ej, Ni*Nj) & adjmask  (half2, 2 cols/op)
            uint32_t af[4];
            af[0] = wgen(hE0, hN0, jA.x, jA.y, r0b & 3u);
            af[1] = wgen(hE1, hN1, jA.x, jA.y, r1b & 3u);
            af[2] = wgen(hE0, hN0, jB.x, jB.y, (r0b >> 8) & 3u);
            af[3] = wgen(hE1, hN1, jB.x, jB.y, (r1b >> 8) & 3u);
            // 8 HMMA + 1 Z-HMMA (ones column)
            #pragma unroll
            for (int np = 0; np < 4; ++np) {
                mma16816(acc[np * 2],     af, bf[np][0], bf[np][1]);
                mma16816(acc[np * 2 + 1], af, bf[np][2], bf[np][3]);
            }
            mma16816(accZ, af, oz0, oz1);
        }
        awc0 = awn0;
        awc1 = awn1;
    }

    // ---- Z: col 0 of the Z-tile (held by tid==0 lanes) ----
    if (tid == 0) {
        float* zb = g_partZ + (size_t)(split * HEADS + head) * NN + i0;
        zb[rA]     = accZ[0];
        zb[rA + 8] = accZ[2];
    }

    // ---- epilogue: store unnormalized partial C ----
    {
        float* cbase = g_partC + (size_t)(split * HEADS + head) * NN * FOUT;
        float* p0 = cbase + (size_t)(i0 + rA) * FOUT + 2 * tid;
        float* p1 = cbase + (size_t)(i0 + rA + 8) * FOUT + 2 * tid;
        #pragma unroll
        for (int np = 0; np < 4; ++np) {
            #pragma unroll
            for (int p = 0; p < 2; ++p) {
                const int nt = np * 2 + p;
                const int cb = np * 16 + p * 8;
                *(float2*)(p0 + cb) = make_float2(acc[nt][0], acc[nt][1]);
                *(float2*)(p1 + cb) = make_float2(acc[nt][2], acc[nt][3]);
            }
        }
    }
}

// ---------------- kernel 3: combine splits, normalize, mean heads ----------
__global__ void __launch_bounds__(256) combine_kernel(float* __restrict__ out) {
    const int idx = blockIdx.x * 256 + threadIdx.x;   // i*64 + f
    const int i = idx >> 6;
    float r = 0.0f;
    #pragma unroll
    for (int h = 0; h < HEADS; ++h) {
        float cs = 0.0f, zs = 0.0f;
        #pragma unroll
        for (int s = 0; s < NSPLIT; ++s) {
            cs += g_partC[(size_t)(s * HEADS + h) * NN * FOUT + idx];
            zs += g_partZ[(size_t)(s * HEADS + h) * NN + i];
        }
        r += cs / zs;
    }
    out[idx] = 0.25f * r;
}

// ---------------- launcher ----------------
extern "C" void kernel_launch(void* const* d_in, const int* in_sizes, int n_in,
                              void* d_out, int out_size) {
    const float* x = nullptr;
    const int*   adj = nullptr;
    const float* W = nullptr;
    const float* a = nullptr;
    for (int i = 0; i < n_in; ++i) {
        switch (in_sizes[i]) {
            case 1048576:  x   = (const float*)d_in[i]; break;
            case 16777216: adj = (const int*)  d_in[i]; break;
            case 65536:    W   = (const float*)d_in[i]; break;
            case 128:      a   = (const float*)d_in[i]; break;
        }
    }
    float* out = (float*)d_out;

    gemm_h_kernel<<<NN / GROWS, 256>>>(x, W, a, adj);
    gat_mma_kernel<<<dim3(NN / ITILE, HEADS, NSPLIT), 256>>>();
    combine_kernel<<<NF / 256, 256>>>(out);
}